// round 12
// baseline (speedup 1.0000x reference)
#include <cuda_runtime.h>
#include <cstdint>
#include <cstddef>

#define N_NODES 100000
#define F_IN    1024
#define H_DIM   256
#define T_DIM   128
#define NNZc    400000
#define E_HE    20000
#define B_GR    16
#define C_CL    64
#define NSEG    (B_GR*C_CL)

// ---------------- device scratch ----------------
__device__ __align__(256) float    g_h0 [(size_t)N_NODES*H_DIM];
__device__ __align__(256) float    g_p  [(size_t)N_NODES*H_DIM];
__device__ __align__(256) float    g_q  [(size_t)N_NODES*H_DIM];
__device__ __align__(256) float    g_he [(size_t)E_HE*H_DIM];
__device__ __align__(256) float    g_out[(size_t)N_NODES*T_DIM];
__device__ __align__(256) float    g_M1 [H_DIM*T_DIM];
__device__ __align__(256) float    g_M2 [H_DIM*T_DIM];
__device__ __align__(256) float    g_M3 [H_DIM*T_DIM];
__device__ __align__(256) float    g_vb [T_DIM];
__device__ __align__(256) float    g_vd [T_DIM];
__device__ __align__(256) float    g_bn [2*H_DIM];
__device__ __align__(256) float    g_scale[H_DIM];
__device__ __align__(256) float    g_shift[H_DIM];
__device__ __align__(256) int      g_D   [N_NODES];
__device__ __align__(256) int      g_Bdeg[E_HE];
__device__ __align__(256) float    g_Dinv[N_NODES];
__device__ __align__(256) float    g_Binv[E_HE];
__device__ __align__(256) unsigned g_pmax[NSEG*T_DIM];
__device__ __align__(256) int      g_pcnt[NSEG];

// ---------------- helpers ----------------
union UF4 { float4 f4; ulonglong2 u2; };

__device__ __forceinline__ void fma2(unsigned long long &d,
                                     unsigned long long a,
                                     unsigned long long b) {
    asm("fma.rn.f32x2 %0, %1, %2, %0;" : "+l"(d) : "l"(a), "l"(b));
}
__device__ __forceinline__ unsigned long long dupf(float x) {
    unsigned u = __float_as_uint(x);
    return ((unsigned long long)u << 32) | (unsigned long long)u;
}
__device__ __forceinline__ unsigned mapf(float f) {
    unsigned u = __float_as_uint(f);
    return (u & 0x80000000u) ? ~u : (u | 0x80000000u);
}
__device__ __forceinline__ float unmapf(unsigned m) {
    unsigned u = (m & 0x80000000u) ? (m & 0x7fffffffu) : ~m;
    return __uint_as_float(u);
}
__device__ __forceinline__ void red_add_v4(float* p, float4 v) {
    asm volatile("red.global.add.v4.f32 [%0], {%1,%2,%3,%4};"
                 :: "l"(p), "f"(v.x), "f"(v.y), "f"(v.z), "f"(v.w) : "memory");
}

// ---------------- zero ----------------
__global__ void k_zero(float* __restrict__ p, int n4) {
    int i = blockIdx.x * blockDim.x + threadIdx.x;
    if (i < n4) ((float4*)p)[i] = make_float4(0.f, 0.f, 0.f, 0.f);
}

// ---------------- tiny weight precompute ----------------
__global__ void k_small_gemm(const float* __restrict__ A, const float* __restrict__ B,
                             float* __restrict__ C, int M, int Nn, int K) {
    int j = threadIdx.x, i = blockIdx.x;
    if (j >= Nn || i >= M) return;
    float s = 0.f;
    for (int k = 0; k < K; k++) s += A[i*K + k] * B[k*Nn + j];
    C[i*Nn + j] = s;
}

__global__ void k_make_vecs(const float* __restrict__ lb0, const float* __restrict__ lb1,
                            const float* __restrict__ lb2, const float* __restrict__ cb1,
                            const float* __restrict__ cb2, const float* __restrict__ lw1,
                            const float* __restrict__ lw2) {
    int t = threadIdx.x;  // 128
    float s  = lb0[t] + lb1[t] + lb2[t];
    float s2 = 0.f;
    for (int k = 0; k < H_DIM; k++) {
        s  += cb1[k] * lw1[k*T_DIM + t] + cb2[k] * lw2[k*T_DIM + t];
        s2 += cb1[k] * g_M3[k*T_DIM + t];
    }
    g_vb[t] = s;
    g_vd[t] = s2;
}

// ---------------- degrees ----------------
__global__ void k_degrees(const int* __restrict__ nidx, const int* __restrict__ eidx) {
    int i = blockIdx.x * blockDim.x + threadIdx.x;
    if (i >= NNZc) return;
    atomicAdd(&g_D[nidx[i]], 1);
    atomicAdd(&g_Bdeg[eidx[i]], 1);
}
__global__ void k_inv() {
    int i = blockIdx.x * blockDim.x + threadIdx.x;
    if (i < N_NODES) { int d = g_D[i];    g_Dinv[i] = d > 0 ? 1.f/(float)d : 0.f; }
    if (i < E_HE)    { int b = g_Bdeg[i]; g_Binv[i] = b > 0 ? 1.f/(float)b : 0.f; }
}

// ---------------- BN stats + apply ----------------
__global__ void k_bn_colsum(const float* __restrict__ z) {
    int t = threadIdx.x;                   // column 0..255
    int nb = gridDim.x;
    int rows = (N_NODES + nb - 1) / nb;
    int r0 = blockIdx.x * rows;
    int r1 = min(r0 + rows, N_NODES);
    float s = 0.f, s2 = 0.f;
    for (int r = r0; r < r1; r++) {
        float v = z[(size_t)r * H_DIM + t];
        s += v; s2 += v * v;
    }
    atomicAdd(&g_bn[t], s);
    atomicAdd(&g_bn[H_DIM + t], s2);
}
__global__ void k_bn_finalize(const float* __restrict__ g1, const float* __restrict__ be1) {
    int t = threadIdx.x;
    float invN = 1.f / (float)N_NODES;
    float mu = g_bn[t] * invN;
    float var = g_bn[H_DIM + t] * invN - mu * mu;
    float sc = g1[t] * rsqrtf(var + 1e-5f);
    g_scale[t] = sc;
    g_shift[t] = be1[t] - mu * sc;
}
__global__ void k_bn_apply() {   // h0 = relu(z*scale+shift), in place on g_h0
    int i = blockIdx.x * blockDim.x + threadIdx.x;   // float4 index
    const int n4 = (int)((size_t)N_NODES * H_DIM / 4);
    if (i >= n4) return;
    int c4 = i & 63;
    float4 v  = ((float4*)g_h0)[i];
    float4 sc = ((float4*)g_scale)[c4];
    float4 sh = ((float4*)g_shift)[c4];
    v.x = fmaxf(v.x*sc.x + sh.x, 0.f);
    v.y = fmaxf(v.y*sc.y + sh.y, 0.f);
    v.z = fmaxf(v.z*sc.z + sh.z, 0.f);
    v.w = fmaxf(v.w*sc.w + sh.w, 0.f);
    ((float4*)g_h0)[i] = v;
}

// ---------------- scatter: dst[dIdx[i]] += scale[sIdx[i]] * src[sIdx[i]] ----
__global__ void k_scatter(const float* __restrict__ src,
                          const float* __restrict__ srcScale,   // nullable
                          const int* __restrict__ sIdx,
                          const int* __restrict__ dIdx,
                          float* __restrict__ dst) {
    int tid = threadIdx.x;
    int edge = blockIdx.x * 4 + (tid >> 6);
    if (edge >= NNZc) return;
    int c4 = tid & 63;
    int sr = sIdx[edge];
    int dr = dIdx[edge];
    float sc = srcScale ? srcScale[sr] : 1.f;
    float4 v = ((const float4*)(src + (size_t)sr * H_DIM))[c4];
    v.x *= sc; v.y *= sc; v.z *= sc; v.w *= sc;
    red_add_v4(dst + (size_t)dr * H_DIM + c4 * 4, v);
}

// ---------------- main f32x2 GEMM: C[M,Nn] (+)= diag(rowScale)*A@B (+bias)(+gate*vd)
__global__ void __launch_bounds__(256)
gemm_f32x2(const float* __restrict__ A, const float* __restrict__ Bw,
           float* __restrict__ C, const int M, const int Nn, const int K,
           const float* __restrict__ rowScale,
           const float* __restrict__ bias,
           const float* __restrict__ vdvec, const int* __restrict__ gateD,
           const int accumulate)
{
    __shared__ unsigned long long As2[2][16][128];
    __shared__ float              Bs [2][16][128];

    const int tid = threadIdx.x;
    const int rowBase = blockIdx.y << 7;
    const int colBase = blockIdx.x << 7;

    const int aRow = tid >> 2;
    const int aCol = (tid & 3) << 2;
    const int bRow = tid >> 5;
    const int bCol = (tid & 31) << 2;
    const int ty = tid >> 4;
    const int tx = tid & 15;

    const int r0 = rowBase + aRow;
    const int r1 = r0 + 64;
    float rs0 = 1.f, rs1 = 1.f;
    if (rowScale) {
        rs0 = (r0 < M) ? rowScale[r0] : 0.f;
        rs1 = (r1 < M) ? rowScale[r1] : 0.f;
    }

    const float4 z4 = make_float4(0.f, 0.f, 0.f, 0.f);
    float4 a0, a1, b0, b1;

    a0 = (r0 < M) ? *(const float4*)(A + (size_t)r0 * K + aCol) : z4;
    a1 = (r1 < M) ? *(const float4*)(A + (size_t)r1 * K + aCol) : z4;
    b0 = *(const float4*)(Bw + (size_t)bRow * Nn + colBase + bCol);
    b1 = *(const float4*)(Bw + (size_t)(bRow + 8) * Nn + colBase + bCol);

    As2[0][aCol+0][aRow]    = dupf(a0.x * rs0);
    As2[0][aCol+1][aRow]    = dupf(a0.y * rs0);
    As2[0][aCol+2][aRow]    = dupf(a0.z * rs0);
    As2[0][aCol+3][aRow]    = dupf(a0.w * rs0);
    As2[0][aCol+0][aRow+64] = dupf(a1.x * rs1);
    As2[0][aCol+1][aRow+64] = dupf(a1.y * rs1);
    As2[0][aCol+2][aRow+64] = dupf(a1.z * rs1);
    As2[0][aCol+3][aRow+64] = dupf(a1.w * rs1);
    *(float4*)&Bs[0][bRow][bCol]   = b0;
    *(float4*)&Bs[0][bRow+8][bCol] = b1;
    __syncthreads();

    unsigned long long acc[8][4];
#pragma unroll
    for (int r = 0; r < 8; r++)
#pragma unroll
        for (int p = 0; p < 4; p++) acc[r][p] = 0ull;

    const int nT = K >> 4;
    int buf = 0;
    for (int kt = 0; kt < nT; kt++) {
        if (kt + 1 < nT) {
            const int kk = (kt + 1) << 4;
            a0 = (r0 < M) ? *(const float4*)(A + (size_t)r0 * K + kk + aCol) : z4;
            a1 = (r1 < M) ? *(const float4*)(A + (size_t)r1 * K + kk + aCol) : z4;
            b0 = *(const float4*)(Bw + (size_t)(kk + bRow) * Nn + colBase + bCol);
            b1 = *(const float4*)(Bw + (size_t)(kk + bRow + 8) * Nn + colBase + bCol);
        }
#pragma unroll
        for (int k = 0; k < 16; k++) {
            unsigned long long av[8];
            const float4* As4 = (const float4*)(&As2[buf][k][0]);
#pragma unroll
            for (int ii = 0; ii < 4; ii++) {
                UF4 u; u.f4 = As4[(ty << 2) + ii];
                av[2*ii]   = u.u2.x;
                av[2*ii+1] = u.u2.y;
            }
            const float4* Bs4 = (const float4*)(&Bs[buf][k][0]);
            UF4 ub0, ub1;
            ub0.f4 = Bs4[(tx << 1)];
            ub1.f4 = Bs4[(tx << 1) + 1];
#pragma unroll
            for (int r = 0; r < 8; r++) {
                fma2(acc[r][0], av[r], ub0.u2.x);
                fma2(acc[r][1], av[r], ub0.u2.y);
                fma2(acc[r][2], av[r], ub1.u2.x);
                fma2(acc[r][3], av[r], ub1.u2.y);
            }
        }
        if (kt + 1 < nT) {
            __syncthreads();
            const int nb = buf ^ 1;
            As2[nb][aCol+0][aRow]    = dupf(a0.x * rs0);
            As2[nb][aCol+1][aRow]    = dupf(a0.y * rs0);
            As2[nb][aCol+2][aRow]    = dupf(a0.z * rs0);
            As2[nb][aCol+3][aRow]    = dupf(a0.w * rs0);
            As2[nb][aCol+0][aRow+64] = dupf(a1.x * rs1);
            As2[nb][aCol+1][aRow+64] = dupf(a1.y * rs1);
            As2[nb][aCol+2][aRow+64] = dupf(a1.z * rs1);
            As2[nb][aCol+3][aRow+64] = dupf(a1.w * rs1);
            *(float4*)&Bs[nb][bRow][bCol]   = b0;
            *(float4*)&Bs[nb][bRow+8][bCol] = b1;
            __syncthreads();
            buf = nb;
        }
    }

    // ---- epilogue ----
    const int col0 = colBase + (tx << 3);
    float bv[8], dv[8];
    if (bias) {
#pragma unroll
        for (int j = 0; j < 8; j++) bv[j] = bias[col0 + j];
    }
    if (vdvec) {
#pragma unroll
        for (int j = 0; j < 8; j++) dv[j] = vdvec[col0 + j];
    }
#pragma unroll
    for (int r = 0; r < 8; r++) {
        int row = rowBase + (ty << 3) + r;
        if (row >= M) continue;
        float vals[8];
#pragma unroll
        for (int p = 0; p < 4; p++) {
            vals[2*p]   = __uint_as_float((unsigned)(acc[r][p] & 0xffffffffull));
            vals[2*p+1] = __uint_as_float((unsigned)(acc[r][p] >> 32));
        }
        if (bias) {
#pragma unroll
            for (int j = 0; j < 8; j++) vals[j] += bv[j];
        }
        if (vdvec && gateD[row] > 0) {
#pragma unroll
            for (int j = 0; j < 8; j++) vals[j] += dv[j];
        }
        float* Crow = C + (size_t)row * Nn + col0;
        if (accumulate) {
            float4 c0 = *(float4*)(Crow);
            float4 c1 = *(float4*)(Crow + 4);
            vals[0]+=c0.x; vals[1]+=c0.y; vals[2]+=c0.z; vals[3]+=c0.w;
            vals[4]+=c1.x; vals[5]+=c1.y; vals[6]+=c1.z; vals[7]+=c1.w;
        }
        *(float4*)(Crow)     = make_float4(vals[0], vals[1], vals[2], vals[3]);
        *(float4*)(Crow + 4) = make_float4(vals[4], vals[5], vals[6], vals[7]);
    }
}

// ---------------- pooling ----------------
__global__ void k_pool(const int* __restrict__ batch, const int* __restrict__ clusters) {
    int n = blockIdx.x;                  // node
    int t = threadIdx.x;                 // col 0..127
    int seg = batch[n] * C_CL + clusters[n];
    unsigned m = mapf(g_out[(size_t)n * T_DIM + t]);
    atomicMax(&g_pmax[seg * T_DIM + t], m);
    if (t == 0) atomicAdd(&g_pcnt[seg], 1);
}
__global__ void k_pool_out(float* __restrict__ out) {
    int i = blockIdx.x * blockDim.x + threadIdx.x;
    if (i >= NSEG * T_DIM) return;
    out[i] = (g_pcnt[i >> 7] > 0) ? unmapf(g_pmax[i]) : 0.f;
}

// ---------------- launch ----------------
static void* dev_ptr(const void* sym) { void* p = nullptr; cudaGetSymbolAddress(&p, sym); return p; }

extern "C" void kernel_launch(void* const* d_in, const int* in_sizes, int n_in,
                              void* d_out, int out_size) {
    const float* x    = (const float*)d_in[0];
    const int* nidx   = (const int*)d_in[1];
    const int* eidx   = (const int*)d_in[2];
    const int* batch  = (const int*)d_in[3];
    const int* clus   = (const int*)d_in[4];
    const float* W1   = (const float*)d_in[8];
    // b1 (d_in[9]) cancels in BN
    const float* g1   = (const float*)d_in[10];
    const float* be1  = (const float*)d_in[11];
    const float* lw0  = (const float*)d_in[12];
    const float* lb0  = (const float*)d_in[13];
    const float* cW1  = (const float*)d_in[14];
    const float* cb1  = (const float*)d_in[15];
    const float* lw1  = (const float*)d_in[16];
    const float* lb1  = (const float*)d_in[17];
    const float* cW2  = (const float*)d_in[18];
    const float* cb2  = (const float*)d_in[19];
    const float* lw2  = (const float*)d_in[20];
    const float* lb2  = (const float*)d_in[21];
    float* out = (float*)d_out;

    float* p_h0 = (float*)dev_ptr(g_h0);
    float* p_p  = (float*)dev_ptr(g_p);
    float* p_q  = (float*)dev_ptr(g_q);
    float* p_he = (float*)dev_ptr(g_he);
    float* p_out= (float*)dev_ptr(g_out);
    float* p_M1 = (float*)dev_ptr(g_M1);
    float* p_M2 = (float*)dev_ptr(g_M2);
    float* p_M3 = (float*)dev_ptr(g_M3);
    float* p_vb = (float*)dev_ptr(g_vb);
    float* p_vd = (float*)dev_ptr(g_vd);
    float* p_bn = (float*)dev_ptr(g_bn);
    int*   p_D  = (int*)dev_ptr(g_D);
    int*   p_Bd = (int*)dev_ptr(g_Bdeg);
    float* p_Di = (float*)dev_ptr(g_Dinv);
    float* p_Bi = (float*)dev_ptr(g_Binv);
    float* p_pm = (float*)dev_ptr(g_pmax);
    float* p_pc = (float*)dev_ptr(g_pcnt);

    // --- zero scratch ---
    auto zero = [](float* p, size_t nfloats) {
        int n4 = (int)(nfloats / 4);
        k_zero<<<(n4 + 255) / 256, 256>>>(p, n4);
    };
    zero(p_p,  (size_t)N_NODES * H_DIM);
    zero(p_q,  (size_t)N_NODES * H_DIM);
    zero(p_he, (size_t)E_HE * H_DIM);
    zero(p_bn, 2 * H_DIM);
    zero(p_pm, NSEG * T_DIM);
    zero(p_pc, NSEG);
    zero((float*)p_D,  N_NODES);
    zero((float*)p_Bd, E_HE);

    // --- degrees ---
    k_degrees<<<(NNZc + 255) / 256, 256>>>(nidx, eidx);
    k_inv<<<(N_NODES + 255) / 256, 256>>>();

    // --- folded weights ---
    k_small_gemm<<<H_DIM, T_DIM>>>(cW2, lw2, p_M3, H_DIM, T_DIM, H_DIM);
    k_small_gemm<<<H_DIM, T_DIM>>>(cW1, lw1, p_M1, H_DIM, T_DIM, H_DIM);
    k_small_gemm<<<H_DIM, T_DIM>>>(cW1, p_M3, p_M2, H_DIM, T_DIM, H_DIM);
    k_make_vecs<<<1, T_DIM>>>(lb0, lb1, lb2, cb1, cb2, lw1, lw2);

    // --- GEMM1: z = x @ W1 -> g_h0 ---
    {
        dim3 grid(H_DIM / 128, (N_NODES + 127) / 128);
        gemm_f32x2<<<grid, 256>>>(x, W1, p_h0, N_NODES, H_DIM, F_IN,
                                  nullptr, nullptr, nullptr, nullptr, 0);
    }

    // --- BN ---
    k_bn_colsum<<<512, H_DIM>>>(p_h0);
    k_bn_finalize<<<1, H_DIM>>>(g1, be1);
    {
        int n4 = (int)((size_t)N_NODES * H_DIM / 4);
        k_bn_apply<<<(n4 + 255) / 256, 256>>>();
    }

    // --- propagation 1: he = S h0 ; p = S^T (Binv*he) ---
    k_scatter<<<(NNZc + 3) / 4, 256>>>(p_h0, nullptr, nidx, eidx, p_he);
    k_scatter<<<(NNZc + 3) / 4, 256>>>(p_he, p_Bi, eidx, nidx, p_p);

    // --- propagation 2: he2 = S (Dinv*p) ; q = S^T (Binv*he2) ---
    zero(p_he, (size_t)E_HE * H_DIM);
    k_scatter<<<(NNZc + 3) / 4, 256>>>(p_p,  p_Di, nidx, eidx, p_he);
    k_scatter<<<(NNZc + 3) / 4, 256>>>(p_he, p_Bi, eidx, nidx, p_q);

    // --- out = h0@lw0 + vb + 1{D>0} vd ; += (Dinv p)@M1 ; += (Dinv q)@M2 ---
    {
        dim3 grid(T_DIM / 128, (N_NODES + 127) / 128);
        gemm_f32x2<<<grid, 256>>>(p_h0, lw0, p_out, N_NODES, T_DIM, H_DIM,
                                  nullptr, p_vb, p_vd, p_D, 0);
        gemm_f32x2<<<grid, 256>>>(p_p, p_M1, p_out, N_NODES, T_DIM, H_DIM,
                                  p_Di, nullptr, nullptr, nullptr, 1);
        gemm_f32x2<<<grid, 256>>>(p_q, p_M2, p_out, N_NODES, T_DIM, H_DIM,
                                  p_Di, nullptr, nullptr, nullptr, 1);
    }

    // --- pooling ---
    k_pool<<<N_NODES, T_DIM>>>(batch, clus);
    k_pool_out<<<(NSEG * T_DIM + 255) / 256, 256>>>(out);
}

// round 13
// speedup vs baseline: 1.1771x; 1.1771x over previous
#include <cuda_runtime.h>
#include <cstdint>
#include <cstddef>

#define N_NODES 100000
#define F_IN    1024
#define H_DIM   256
#define T_DIM   128
#define NNZc    400000
#define E_HE    20000
#define B_GR    16
#define C_CL    64
#define NSEG    (B_GR*C_CL)

// ---------------- device scratch ----------------
__device__ __align__(256) float    g_h0 [(size_t)N_NODES*H_DIM];
__device__ __align__(256) float    g_p  [(size_t)N_NODES*H_DIM];
__device__ __align__(256) float    g_q  [(size_t)N_NODES*H_DIM];
__device__ __align__(256) float    g_he [(size_t)E_HE*H_DIM];
__device__ __align__(256) float    g_out[(size_t)N_NODES*T_DIM];
__device__ __align__(256) float    g_M1 [H_DIM*T_DIM];
__device__ __align__(256) float    g_M2 [H_DIM*T_DIM];
__device__ __align__(256) float    g_M3 [H_DIM*T_DIM];
__device__ __align__(256) float    g_vb [T_DIM];
__device__ __align__(256) float    g_vd [T_DIM];
__device__ __align__(256) float    g_bn [2*H_DIM];
__device__ __align__(256) float    g_scale[H_DIM];
__device__ __align__(256) float    g_shift[H_DIM];
__device__ __align__(256) int      g_D   [N_NODES];
__device__ __align__(256) int      g_Bdeg[E_HE];
__device__ __align__(256) float    g_Dinv[N_NODES];
__device__ __align__(256) float    g_Binv[E_HE];
__device__ __align__(256) unsigned g_pmax[NSEG*T_DIM];
__device__ __align__(256) int      g_pcnt[NSEG];

// ---------------- helpers ----------------
union UF4 { float4 f4; ulonglong2 u2; };

__device__ __forceinline__ void fma2(unsigned long long &d,
                                     unsigned long long a,
                                     unsigned long long b) {
    asm("fma.rn.f32x2 %0, %1, %2, %0;" : "+l"(d) : "l"(a), "l"(b));
}
__device__ __forceinline__ unsigned long long dupf(float x) {
    unsigned u = __float_as_uint(x);
    return ((unsigned long long)u << 32) | (unsigned long long)u;
}
__device__ __forceinline__ unsigned mapf(float f) {
    unsigned u = __float_as_uint(f);
    return (u & 0x80000000u) ? ~u : (u | 0x80000000u);
}
__device__ __forceinline__ float unmapf(unsigned m) {
    unsigned u = (m & 0x80000000u) ? (m & 0x7fffffffu) : ~m;
    return __uint_as_float(u);
}
__device__ __forceinline__ void red_add_v4(float* p, float4 v) {
    asm volatile("red.global.add.v4.f32 [%0], {%1,%2,%3,%4};"
                 :: "l"(p), "f"(v.x), "f"(v.y), "f"(v.z), "f"(v.w) : "memory");
}

// ---------------- zero ----------------
__global__ void k_zero(float* __restrict__ p, int n4) {
    int i = blockIdx.x * blockDim.x + threadIdx.x;
    if (i < n4) ((float4*)p)[i] = make_float4(0.f, 0.f, 0.f, 0.f);
}

// ---------------- tiny weight precompute ----------------
__global__ void k_small_gemm(const float* __restrict__ A, const float* __restrict__ B,
                             float* __restrict__ C, int M, int Nn, int K) {
    int j = threadIdx.x, i = blockIdx.x;
    if (j >= Nn || i >= M) return;
    float s = 0.f;
    for (int k = 0; k < K; k++) s += A[i*K + k] * B[k*Nn + j];
    C[i*Nn + j] = s;
}

__global__ void k_make_vecs(const float* __restrict__ lb0, const float* __restrict__ lb1,
                            const float* __restrict__ lb2, const float* __restrict__ cb1,
                            const float* __restrict__ cb2, const float* __restrict__ lw1,
                            const float* __restrict__ lw2) {
    int t = threadIdx.x;  // 128
    float s  = lb0[t] + lb1[t] + lb2[t];
    float s2 = 0.f;
    for (int k = 0; k < H_DIM; k++) {
        s  += cb1[k] * lw1[k*T_DIM + t] + cb2[k] * lw2[k*T_DIM + t];
        s2 += cb1[k] * g_M3[k*T_DIM + t];
    }
    g_vb[t] = s;
    g_vd[t] = s2;
}

// ---------------- degrees ----------------
__global__ void k_degrees(const int* __restrict__ nidx, const int* __restrict__ eidx) {
    int i = blockIdx.x * blockDim.x + threadIdx.x;
    if (i >= NNZc) return;
    atomicAdd(&g_D[nidx[i]], 1);
    atomicAdd(&g_Bdeg[eidx[i]], 1);
}
__global__ void k_inv() {
    int i = blockIdx.x * blockDim.x + threadIdx.x;
    if (i < N_NODES) { int d = g_D[i];    g_Dinv[i] = d > 0 ? 1.f/(float)d : 0.f; }
    if (i < E_HE)    { int b = g_Bdeg[i]; g_Binv[i] = b > 0 ? 1.f/(float)b : 0.f; }
}

// ---------------- BN stats + apply ----------------
__global__ void k_bn_colsum(const float* __restrict__ z) {
    int t = threadIdx.x;                   // column 0..255
    int nb = gridDim.x;
    int rows = (N_NODES + nb - 1) / nb;
    int r0 = blockIdx.x * rows;
    int r1 = min(r0 + rows, N_NODES);
    float s = 0.f, s2 = 0.f;
    for (int r = r0; r < r1; r++) {
        float v = z[(size_t)r * H_DIM + t];
        s += v; s2 += v * v;
    }
    atomicAdd(&g_bn[t], s);
    atomicAdd(&g_bn[H_DIM + t], s2);
}
__global__ void k_bn_finalize(const float* __restrict__ g1, const float* __restrict__ be1) {
    int t = threadIdx.x;
    float invN = 1.f / (float)N_NODES;
    float mu = g_bn[t] * invN;
    float var = g_bn[H_DIM + t] * invN - mu * mu;
    float sc = g1[t] * rsqrtf(var + 1e-5f);
    g_scale[t] = sc;
    g_shift[t] = be1[t] - mu * sc;
}
__global__ void k_bn_apply() {   // h0 = relu(z*scale+shift), in place on g_h0
    int i = blockIdx.x * blockDim.x + threadIdx.x;   // float4 index
    const int n4 = (int)((size_t)N_NODES * H_DIM / 4);
    if (i >= n4) return;
    int c4 = i & 63;
    float4 v  = ((float4*)g_h0)[i];
    float4 sc = ((float4*)g_scale)[c4];
    float4 sh = ((float4*)g_shift)[c4];
    v.x = fmaxf(v.x*sc.x + sh.x, 0.f);
    v.y = fmaxf(v.y*sc.y + sh.y, 0.f);
    v.z = fmaxf(v.z*sc.z + sh.z, 0.f);
    v.w = fmaxf(v.w*sc.w + sh.w, 0.f);
    ((float4*)g_h0)[i] = v;
}

// ---------------- scatter: dst[dIdx[i]] += scale[sIdx[i]] * src[sIdx[i]] ----
__global__ void k_scatter(const float* __restrict__ src,
                          const float* __restrict__ srcScale,   // nullable
                          const int* __restrict__ sIdx,
                          const int* __restrict__ dIdx,
                          float* __restrict__ dst) {
    int tid = threadIdx.x;
    int edge = blockIdx.x * 4 + (tid >> 6);
    if (edge >= NNZc) return;
    int c4 = tid & 63;
    int sr = sIdx[edge];
    int dr = dIdx[edge];
    float sc = srcScale ? srcScale[sr] : 1.f;
    float4 v = ((const float4*)(src + (size_t)sr * H_DIM))[c4];
    v.x *= sc; v.y *= sc; v.z *= sc; v.w *= sc;
    red_add_v4(dst + (size_t)dr * H_DIM + c4 * 4, v);
}

// ---------------- GEMM1: C[M,Nn] = A[M,K]@B[K,Nn] (f32x2 microkernel) ------
__global__ void __launch_bounds__(256)
gemm_f32x2(const float* __restrict__ A, const float* __restrict__ Bw,
           float* __restrict__ C, const int M, const int Nn, const int K)
{
    __shared__ unsigned long long As2[2][16][128];
    __shared__ float              Bs [2][16][128];

    const int tid = threadIdx.x;
    const int rowBase = blockIdx.y << 7;
    const int colBase = blockIdx.x << 7;

    const int aRow = tid >> 2;
    const int aCol = (tid & 3) << 2;
    const int bRow = tid >> 5;
    const int bCol = (tid & 31) << 2;
    const int ty = tid >> 4;
    const int tx = tid & 15;

    const int r0 = rowBase + aRow;
    const int r1 = r0 + 64;

    const float4 z4 = make_float4(0.f, 0.f, 0.f, 0.f);
    float4 a0, a1, b0, b1;

    a0 = (r0 < M) ? *(const float4*)(A + (size_t)r0 * K + aCol) : z4;
    a1 = (r1 < M) ? *(const float4*)(A + (size_t)r1 * K + aCol) : z4;
    b0 = *(const float4*)(Bw + (size_t)bRow * Nn + colBase + bCol);
    b1 = *(const float4*)(Bw + (size_t)(bRow + 8) * Nn + colBase + bCol);

    As2[0][aCol+0][aRow]    = dupf(a0.x);
    As2[0][aCol+1][aRow]    = dupf(a0.y);
    As2[0][aCol+2][aRow]    = dupf(a0.z);
    As2[0][aCol+3][aRow]    = dupf(a0.w);
    As2[0][aCol+0][aRow+64] = dupf(a1.x);
    As2[0][aCol+1][aRow+64] = dupf(a1.y);
    As2[0][aCol+2][aRow+64] = dupf(a1.z);
    As2[0][aCol+3][aRow+64] = dupf(a1.w);
    *(float4*)&Bs[0][bRow][bCol]   = b0;
    *(float4*)&Bs[0][bRow+8][bCol] = b1;
    __syncthreads();

    unsigned long long acc[8][4];
#pragma unroll
    for (int r = 0; r < 8; r++)
#pragma unroll
        for (int p = 0; p < 4; p++) acc[r][p] = 0ull;

    const int nT = K >> 4;
    int buf = 0;
    for (int kt = 0; kt < nT; kt++) {
        if (kt + 1 < nT) {
            const int kk = (kt + 1) << 4;
            a0 = (r0 < M) ? *(const float4*)(A + (size_t)r0 * K + kk + aCol) : z4;
            a1 = (r1 < M) ? *(const float4*)(A + (size_t)r1 * K + kk + aCol) : z4;
            b0 = *(const float4*)(Bw + (size_t)(kk + bRow) * Nn + colBase + bCol);
            b1 = *(const float4*)(Bw + (size_t)(kk + bRow + 8) * Nn + colBase + bCol);
        }
#pragma unroll
        for (int k = 0; k < 16; k++) {
            unsigned long long av[8];
            const float4* As4 = (const float4*)(&As2[buf][k][0]);
#pragma unroll
            for (int ii = 0; ii < 4; ii++) {
                UF4 u; u.f4 = As4[(ty << 2) + ii];
                av[2*ii]   = u.u2.x;
                av[2*ii+1] = u.u2.y;
            }
            const float4* Bs4 = (const float4*)(&Bs[buf][k][0]);
            UF4 ub0, ub1;
            ub0.f4 = Bs4[(tx << 1)];
            ub1.f4 = Bs4[(tx << 1) + 1];
#pragma unroll
            for (int r = 0; r < 8; r++) {
                fma2(acc[r][0], av[r], ub0.u2.x);
                fma2(acc[r][1], av[r], ub0.u2.y);
                fma2(acc[r][2], av[r], ub1.u2.x);
                fma2(acc[r][3], av[r], ub1.u2.y);
            }
        }
        if (kt + 1 < nT) {
            __syncthreads();
            const int nb = buf ^ 1;
            As2[nb][aCol+0][aRow]    = dupf(a0.x);
            As2[nb][aCol+1][aRow]    = dupf(a0.y);
            As2[nb][aCol+2][aRow]    = dupf(a0.z);
            As2[nb][aCol+3][aRow]    = dupf(a0.w);
            As2[nb][aCol+0][aRow+64] = dupf(a1.x);
            As2[nb][aCol+1][aRow+64] = dupf(a1.y);
            As2[nb][aCol+2][aRow+64] = dupf(a1.z);
            As2[nb][aCol+3][aRow+64] = dupf(a1.w);
            *(float4*)&Bs[nb][bRow][bCol]   = b0;
            *(float4*)&Bs[nb][bRow+8][bCol] = b1;
            __syncthreads();
            buf = nb;
        }
    }

    const int col0 = colBase + (tx << 3);
#pragma unroll
    for (int r = 0; r < 8; r++) {
        int row = rowBase + (ty << 3) + r;
        if (row >= M) continue;
        float vals[8];
#pragma unroll
        for (int p = 0; p < 4; p++) {
            vals[2*p]   = __uint_as_float((unsigned)(acc[r][p] & 0xffffffffull));
            vals[2*p+1] = __uint_as_float((unsigned)(acc[r][p] >> 32));
        }
        float* Crow = C + (size_t)row * Nn + col0;
        *(float4*)(Crow)     = make_float4(vals[0], vals[1], vals[2], vals[3]);
        *(float4*)(Crow + 4) = make_float4(vals[4], vals[5], vals[6], vals[7]);
    }
}

// ---------------- fused out-GEMM:
// out = h0@B0 + (Dinv*p)@B1 + (Dinv*q)@B2 + vb + 1{D>0}*vd
// Nn = 128 (one col-tile), K = 256 per segment, 48 k-tiles total.
__global__ void __launch_bounds__(256)
gemm_out_fused(const float* __restrict__ A0, const float* __restrict__ A1,
               const float* __restrict__ A2,
               const float* __restrict__ B0, const float* __restrict__ B1,
               const float* __restrict__ B2,
               float* __restrict__ C,
               const float* __restrict__ rowScale,   // Dinv
               const float* __restrict__ bias,       // vb
               const float* __restrict__ vdvec, const int* __restrict__ gateD)
{
    __shared__ unsigned long long As2[2][16][128];
    __shared__ float              Bs [2][16][128];

    const int tid = threadIdx.x;
    const int rowBase = blockIdx.x << 7;
    const int M = N_NODES, Nn = T_DIM, K = H_DIM;

    const int aRow = tid >> 2;
    const int aCol = (tid & 3) << 2;
    const int bRow = tid >> 5;
    const int bCol = (tid & 31) << 2;
    const int ty = tid >> 4;
    const int tx = tid & 15;

    const int r0 = rowBase + aRow;
    const int r1 = r0 + 64;
    const float rsD0 = (r0 < M) ? rowScale[r0] : 0.f;
    const float rsD1 = (r1 < M) ? rowScale[r1] : 0.f;

    const float4 z4 = make_float4(0.f, 0.f, 0.f, 0.f);
    float4 a0, a1, b0, b1;

    // tile 0: segment 0 (A0/B0, rs=1)
    a0 = (r0 < M) ? *(const float4*)(A0 + (size_t)r0 * K + aCol) : z4;
    a1 = (r1 < M) ? *(const float4*)(A0 + (size_t)r1 * K + aCol) : z4;
    b0 = *(const float4*)(B0 + (size_t)bRow * Nn + bCol);
    b1 = *(const float4*)(B0 + (size_t)(bRow + 8) * Nn + bCol);

    As2[0][aCol+0][aRow]    = dupf(a0.x);
    As2[0][aCol+1][aRow]    = dupf(a0.y);
    As2[0][aCol+2][aRow]    = dupf(a0.z);
    As2[0][aCol+3][aRow]    = dupf(a0.w);
    As2[0][aCol+0][aRow+64] = dupf(a1.x);
    As2[0][aCol+1][aRow+64] = dupf(a1.y);
    As2[0][aCol+2][aRow+64] = dupf(a1.z);
    As2[0][aCol+3][aRow+64] = dupf(a1.w);
    *(float4*)&Bs[0][bRow][bCol]   = b0;
    *(float4*)&Bs[0][bRow+8][bCol] = b1;
    __syncthreads();

    unsigned long long acc[8][4];
#pragma unroll
    for (int r = 0; r < 8; r++)
#pragma unroll
        for (int p = 0; p < 4; p++) acc[r][p] = 0ull;

    const int nT = 3 * (K >> 4);   // 48
    int buf = 0;
    float rsNext0 = 1.f, rsNext1 = 1.f;
    for (int kt = 0; kt < nT; kt++) {
        if (kt + 1 < nT) {
            const int seg2 = (kt + 1) >> 4;
            const int kk   = ((kt + 1) & 15) << 4;
            const float* A = (seg2 == 0) ? A0 : (seg2 == 1) ? A1 : A2;
            const float* B = (seg2 == 0) ? B0 : (seg2 == 1) ? B1 : B2;
            rsNext0 = (seg2 == 0) ? 1.f : rsD0;
            rsNext1 = (seg2 == 0) ? 1.f : rsD1;
            a0 = (r0 < M) ? *(const float4*)(A + (size_t)r0 * K + kk + aCol) : z4;
            a1 = (r1 < M) ? *(const float4*)(A + (size_t)r1 * K + kk + aCol) : z4;
            b0 = *(const float4*)(B + (size_t)(kk + bRow) * Nn + bCol);
            b1 = *(const float4*)(B + (size_t)(kk + bRow + 8) * Nn + bCol);
        }
#pragma unroll
        for (int k = 0; k < 16; k++) {
            unsigned long long av[8];
            const float4* As4 = (const float4*)(&As2[buf][k][0]);
#pragma unroll
            for (int ii = 0; ii < 4; ii++) {
                UF4 u; u.f4 = As4[(ty << 2) + ii];
                av[2*ii]   = u.u2.x;
                av[2*ii+1] = u.u2.y;
            }
            const float4* Bs4 = (const float4*)(&Bs[buf][k][0]);
            UF4 ub0, ub1;
            ub0.f4 = Bs4[(tx << 1)];
            ub1.f4 = Bs4[(tx << 1) + 1];
#pragma unroll
            for (int r = 0; r < 8; r++) {
                fma2(acc[r][0], av[r], ub0.u2.x);
                fma2(acc[r][1], av[r], ub0.u2.y);
                fma2(acc[r][2], av[r], ub1.u2.x);
                fma2(acc[r][3], av[r], ub1.u2.y);
            }
        }
        if (kt + 1 < nT) {
            __syncthreads();
            const int nb = buf ^ 1;
            As2[nb][aCol+0][aRow]    = dupf(a0.x * rsNext0);
            As2[nb][aCol+1][aRow]    = dupf(a0.y * rsNext0);
            As2[nb][aCol+2][aRow]    = dupf(a0.z * rsNext0);
            As2[nb][aCol+3][aRow]    = dupf(a0.w * rsNext0);
            As2[nb][aCol+0][aRow+64] = dupf(a1.x * rsNext1);
            As2[nb][aCol+1][aRow+64] = dupf(a1.y * rsNext1);
            As2[nb][aCol+2][aRow+64] = dupf(a1.z * rsNext1);
            As2[nb][aCol+3][aRow+64] = dupf(a1.w * rsNext1);
            *(float4*)&Bs[nb][bRow][bCol]   = b0;
            *(float4*)&Bs[nb][bRow+8][bCol] = b1;
            __syncthreads();
            buf = nb;
        }
    }

    // ---- epilogue: + vb + gated vd, single write ----
    const int col0 = tx << 3;
    float bv[8], dv[8];
#pragma unroll
    for (int j = 0; j < 8; j++) { bv[j] = bias[col0 + j]; dv[j] = vdvec[col0 + j]; }
#pragma unroll
    for (int r = 0; r < 8; r++) {
        int row = rowBase + (ty << 3) + r;
        if (row >= M) continue;
        float vals[8];
#pragma unroll
        for (int p = 0; p < 4; p++) {
            vals[2*p]   = __uint_as_float((unsigned)(acc[r][p] & 0xffffffffull));
            vals[2*p+1] = __uint_as_float((unsigned)(acc[r][p] >> 32));
        }
        const bool gate = gateD[row] > 0;
#pragma unroll
        for (int j = 0; j < 8; j++) {
            vals[j] += bv[j];
            if (gate) vals[j] += dv[j];
        }
        float* Crow = C + (size_t)row * Nn + col0;
        *(float4*)(Crow)     = make_float4(vals[0], vals[1], vals[2], vals[3]);
        *(float4*)(Crow + 4) = make_float4(vals[4], vals[5], vals[6], vals[7]);
    }
}

// ---------------- pooling ----------------
__global__ void k_pool(const int* __restrict__ batch, const int* __restrict__ clusters) {
    int n = blockIdx.x;                  // node
    int t = threadIdx.x;                 // col 0..127
    int seg = batch[n] * C_CL + clusters[n];
    unsigned m = mapf(g_out[(size_t)n * T_DIM + t]);
    atomicMax(&g_pmax[seg * T_DIM + t], m);
    if (t == 0) atomicAdd(&g_pcnt[seg], 1);
}
__global__ void k_pool_out(float* __restrict__ out) {
    int i = blockIdx.x * blockDim.x + threadIdx.x;
    if (i >= NSEG * T_DIM) return;
    out[i] = (g_pcnt[i >> 7] > 0) ? unmapf(g_pmax[i]) : 0.f;
}

// ---------------- launch ----------------
static void* dev_ptr(const void* sym) { void* p = nullptr; cudaGetSymbolAddress(&p, sym); return p; }

extern "C" void kernel_launch(void* const* d_in, const int* in_sizes, int n_in,
                              void* d_out, int out_size) {
    const float* x    = (const float*)d_in[0];
    const int* nidx   = (const int*)d_in[1];
    const int* eidx   = (const int*)d_in[2];
    const int* batch  = (const int*)d_in[3];
    const int* clus   = (const int*)d_in[4];
    const float* W1   = (const float*)d_in[8];
    // b1 (d_in[9]) cancels in BN
    const float* g1   = (const float*)d_in[10];
    const float* be1  = (const float*)d_in[11];
    const float* lw0  = (const float*)d_in[12];
    const float* lb0  = (const float*)d_in[13];
    const float* cW1  = (const float*)d_in[14];
    const float* cb1  = (const float*)d_in[15];
    const float* lw1  = (const float*)d_in[16];
    const float* lb1  = (const float*)d_in[17];
    const float* cW2  = (const float*)d_in[18];
    const float* cb2  = (const float*)d_in[19];
    const float* lw2  = (const float*)d_in[20];
    const float* lb2  = (const float*)d_in[21];
    float* out = (float*)d_out;

    float* p_h0 = (float*)dev_ptr(g_h0);
    float* p_p  = (float*)dev_ptr(g_p);
    float* p_q  = (float*)dev_ptr(g_q);
    float* p_he = (float*)dev_ptr(g_he);
    float* p_out= (float*)dev_ptr(g_out);
    float* p_M1 = (float*)dev_ptr(g_M1);
    float* p_M2 = (float*)dev_ptr(g_M2);
    float* p_M3 = (float*)dev_ptr(g_M3);
    float* p_vb = (float*)dev_ptr(g_vb);
    float* p_vd = (float*)dev_ptr(g_vd);
    float* p_bn = (float*)dev_ptr(g_bn);
    int*   p_D  = (int*)dev_ptr(g_D);
    int*   p_Bd = (int*)dev_ptr(g_Bdeg);
    float* p_Di = (float*)dev_ptr(g_Dinv);
    float* p_Bi = (float*)dev_ptr(g_Binv);
    float* p_pm = (float*)dev_ptr(g_pmax);
    float* p_pc = (float*)dev_ptr(g_pcnt);

    auto zero = [](float* p, size_t nfloats) {
        int n4 = (int)(nfloats / 4);
        k_zero<<<(n4 + 255) / 256, 256>>>(p, n4);
    };

    // launches 0..4: small zeros (so launch #5 = GEMM1 is ncu's capture target)
    zero(p_bn, 2 * H_DIM);                 // 0
    zero(p_pm, NSEG * T_DIM);              // 1
    zero(p_pc, NSEG);                      // 2
    zero((float*)p_D,  N_NODES);           // 3
    zero((float*)p_Bd, E_HE);              // 4

    // launch 5: GEMM1 z = x @ W1 -> g_h0   (profiled by ncu -s 5 -c 1)
    {
        dim3 grid(H_DIM / 128, (N_NODES + 127) / 128);
        gemm_f32x2<<<grid, 256>>>(x, W1, p_h0, N_NODES, H_DIM, F_IN);
    }

    // remaining zeros
    zero(p_p,  (size_t)N_NODES * H_DIM);
    zero(p_q,  (size_t)N_NODES * H_DIM);
    zero(p_he, (size_t)E_HE * H_DIM);

    // degrees
    k_degrees<<<(NNZc + 255) / 256, 256>>>(nidx, eidx);
    k_inv<<<(N_NODES + 255) / 256, 256>>>();

    // folded weights
    k_small_gemm<<<H_DIM, T_DIM>>>(cW2, lw2, p_M3, H_DIM, T_DIM, H_DIM);
    k_small_gemm<<<H_DIM, T_DIM>>>(cW1, lw1, p_M1, H_DIM, T_DIM, H_DIM);
    k_small_gemm<<<H_DIM, T_DIM>>>(cW1, p_M3, p_M2, H_DIM, T_DIM, H_DIM);
    k_make_vecs<<<1, T_DIM>>>(lb0, lb1, lb2, cb1, cb2, lw1, lw2);

    // BN
    k_bn_colsum<<<512, H_DIM>>>(p_h0);
    k_bn_finalize<<<1, H_DIM>>>(g1, be1);
    {
        int n4 = (int)((size_t)N_NODES * H_DIM / 4);
        k_bn_apply<<<(n4 + 255) / 256, 256>>>();
    }

    // propagation 1: he = S h0 ; p = S^T (Binv*he)
    k_scatter<<<(NNZc + 3) / 4, 256>>>(p_h0, nullptr, nidx, eidx, p_he);
    k_scatter<<<(NNZc + 3) / 4, 256>>>(p_he, p_Bi, eidx, nidx, p_p);

    // propagation 2: he2 = S (Dinv*p) ; q = S^T (Binv*he2)
    zero(p_he, (size_t)E_HE * H_DIM);
    k_scatter<<<(NNZc + 3) / 4, 256>>>(p_p,  p_Di, nidx, eidx, p_he);
    k_scatter<<<(NNZc + 3) / 4, 256>>>(p_he, p_Bi, eidx, nidx, p_q);

    // fused out-GEMM: out = h0@lw0 + (Dinv p)@M1 + (Dinv q)@M2 + vb + 1{D>0} vd
    gemm_out_fused<<<(N_NODES + 127) / 128, 256>>>(
        p_h0, p_p, p_q, lw0, p_M1, p_M2, p_out, p_Di, p_vb, p_vd, p_D);

    // pooling
    k_pool<<<N_NODES, T_DIM>>>(batch, clus);
    k_pool_out<<<(NSEG * T_DIM + 255) / 256, 256>>>(out);
}